// round 1
// baseline (speedup 1.0000x reference)
#include <cuda_runtime.h>

#define THREADS 256

// Shared-memory layout (all strides odd => conflict-free for our lane mappings)
constexpr int SA_STRIDE = 95;               // attn plane: 64 rows, data cols [15,79)
constexpr int SA_SIZE   = 64 * SA_STRIDE;   // 6080
constexpr int SX_STRIDE = 69;               // x plane padded by 2: 68 rows
constexpr int SX_SIZE   = 68 * SX_STRIDE;   // 4692
constexpr int ST_STRIDE = 65;               // tmp plane: 64 rows (unpadded, predicated reads)
constexpr int ST_SIZE   = 64 * ST_STRIDE;   // 4160
constexpr int UNION_SIZE  = (SX_SIZE > ST_SIZE) ? SX_SIZE : ST_SIZE;  // 4692
constexpr int SMEM_FLOATS = SA_SIZE + UNION_SIZE;                     // 10772 -> 43088 B

// Horizontal 1xK depthwise conv: s_a (biased attn) -> s_t.
// Thread t handles row = t&63, 16 consecutive cols starting at ((t>>6)<<4).
// Lanes within a warp hit distinct rows; SA_STRIDE%32==31, ST_STRIDE%32==1 => no conflicts.
template<int K>
__device__ __forceinline__ void hpass(const float* __restrict__ s_a,
                                      float* __restrict__ s_t,
                                      const float* __restrict__ wg,
                                      float bias, int tid)
{
    float w[K];
#pragma unroll
    for (int j = 0; j < K; j++) w[j] = __ldg(wg + j);
    const int row  = tid & 63;
    const int col0 = (tid >> 6) << 4;
    float acc[16];
#pragma unroll
    for (int o = 0; o < 16; o++) acc[o] = bias;
    const float* sr = s_a + row * SA_STRIDE + 15 + col0 - (K / 2);
#pragma unroll
    for (int i = 0; i < K + 15; i++) {
        const float v = sr[i];
#pragma unroll
        for (int o = 0; o < 16; o++) {
            const int j = i - o;
            if (j >= 0 && j < K) acc[o] = fmaf(v, w[j], acc[o]);
        }
    }
    float* st = s_t + row * ST_STRIDE + col0;
#pragma unroll
    for (int o = 0; o < 16; o++) st[o] = acc[o];
}

// Vertical Kx1 depthwise conv: s_t -> global output section (coalesced stores).
// Thread t handles col = t&63, 16 consecutive rows starting at ((t>>6)<<4).
// Zero-padding handled by predicated loads (out-of-range row -> 0).
template<int K>
__device__ __forceinline__ void vpass(const float* __restrict__ s_t,
                                      const float* __restrict__ wg,
                                      float bias,
                                      float* __restrict__ osec, int tid)
{
    float w[K];
#pragma unroll
    for (int j = 0; j < K; j++) w[j] = __ldg(wg + j);
    const int col = tid & 63;
    const int r0  = (tid >> 6) << 4;
    float acc[16];
#pragma unroll
    for (int o = 0; o < 16; o++) acc[o] = bias;
#pragma unroll
    for (int i = 0; i < K + 15; i++) {
        const int ridx = r0 - (K / 2) + i;
        float v = 0.0f;
        if (ridx >= 0 && ridx < 64) v = s_t[ridx * ST_STRIDE + col];
#pragma unroll
        for (int o = 0; o < 16; o++) {
            const int j = i - o;
            if (j >= 0 && j < K) acc[o] = fmaf(v, w[j], acc[o]);
        }
    }
#pragma unroll
    for (int o = 0; o < 16; o++) osec[(r0 + o) * 64 + col] = acc[o];
}

__global__ __launch_bounds__(THREADS, 3)
void lka_kernel(const float* __restrict__ x,
                const float* __restrict__ w0,  const float* __restrict__ b0,
                const float* __restrict__ w01, const float* __restrict__ b01,
                const float* __restrict__ w02, const float* __restrict__ b02,
                const float* __restrict__ w11, const float* __restrict__ b11,
                const float* __restrict__ w12, const float* __restrict__ b12,
                const float* __restrict__ w21, const float* __restrict__ b21,
                const float* __restrict__ w22, const float* __restrict__ b22,
                float* __restrict__ out)
{
    __shared__ float sm[SMEM_FLOATS];
    float* s_a = sm;              // attn plane (lives across all branches)
    float* s_x = sm + SA_SIZE;    // x plane   (dead after 5x5)   } union
    float* s_t = sm + SA_SIZE;    // h-conv tmp (per branch)      } union

    const int tid = threadIdx.x;
    const int bc  = blockIdx.x;        // b*128 + c
    const int c   = bc & 127;
    const int b   = bc >> 7;

    const float* xp = x + (long)bc * 4096;
    float* outb = out + (long)b * (640 * 4096) + (long)c * 4096;

    // Zero all smem (provides zero padding for s_x borders and s_a side columns)
    for (int i = tid; i < SMEM_FLOATS; i += THREADS) sm[i] = 0.0f;
    __syncthreads();

    // Load x plane into padded smem; write pass-through section 0 (coalesced)
#pragma unroll
    for (int k = 0; k < 16; k++) {
        const int i = tid + k * THREADS;
        const float v = xp[i];
        outb[i] = v;
        s_x[((i >> 6) + 2) * SX_STRIDE + (i & 63) + 2] = v;
    }
    __syncthreads();

    // 5x5 depthwise conv: s_x -> s_a (includes bias, matching reference 'attn')
    {
        float w[25];
#pragma unroll
        for (int j = 0; j < 25; j++) w[j] = __ldg(w0 + c * 25 + j);
        const float bias = __ldg(b0 + c);
        const int row  = tid & 63;
        const int col0 = (tid >> 6) << 4;
        float acc[16];
#pragma unroll
        for (int o = 0; o < 16; o++) acc[o] = bias;
#pragma unroll
        for (int r = 0; r < 5; r++) {
            const float* sr = s_x + (row + r) * SX_STRIDE + col0;
#pragma unroll
            for (int i = 0; i < 20; i++) {
                const float v = sr[i];
#pragma unroll
                for (int o = 0; o < 16; o++) {
                    const int j = i - o;
                    if (j >= 0 && j < 5) acc[o] = fmaf(v, w[r * 5 + j], acc[o]);
                }
            }
        }
        float* sa = s_a + row * SA_STRIDE + 15 + col0;
#pragma unroll
        for (int o = 0; o < 16; o++) sa[o] = acc[o];
    }
    __syncthreads();   // also guards s_x (union with s_t) against hpass writes

    // Section 1: attn, copied coalesced from smem
    {
        float* out1 = outb + 128 * 4096;
#pragma unroll
        for (int k = 0; k < 16; k++) {
            const int i = tid + k * THREADS;
            out1[i] = s_a[(i >> 6) * SA_STRIDE + 15 + (i & 63)];
        }
    }

    // Branch 0: 1x7 then 7x1 -> section 2
    hpass<7>(s_a, s_t, w01 + c * 7, __ldg(b01 + c), tid);
    __syncthreads();
    vpass<7>(s_t, w02 + c * 7, __ldg(b02 + c), outb + 2 * 128 * 4096, tid);
    __syncthreads();

    // Branch 1: 1x15 then 15x1 -> section 3
    hpass<15>(s_a, s_t, w11 + c * 15, __ldg(b11 + c), tid);
    __syncthreads();
    vpass<15>(s_t, w12 + c * 15, __ldg(b12 + c), outb + 3 * 128 * 4096, tid);
    __syncthreads();

    // Branch 2: 1x31 then 31x1 -> section 4
    hpass<31>(s_a, s_t, w21 + c * 31, __ldg(b21 + c), tid);
    __syncthreads();
    vpass<31>(s_t, w22 + c * 31, __ldg(b22 + c), outb + 4 * 128 * 4096, tid);
}

extern "C" void kernel_launch(void* const* d_in, const int* in_sizes, int n_in,
                              void* d_out, int out_size)
{
    lka_kernel<<<32 * 128, THREADS>>>(
        (const float*)d_in[0],
        (const float*)d_in[1],  (const float*)d_in[2],
        (const float*)d_in[3],  (const float*)d_in[4],
        (const float*)d_in[5],  (const float*)d_in[6],
        (const float*)d_in[7],  (const float*)d_in[8],
        (const float*)d_in[9],  (const float*)d_in[10],
        (const float*)d_in[11], (const float*)d_in[12],
        (const float*)d_in[13], (const float*)d_in[14],
        (float*)d_out);
}